// round 10
// baseline (speedup 1.0000x reference)
#include <cuda_runtime.h>
#include <math.h>
#include <stdint.h>

#define NSEQ 320
#define C 128
#define H 4
#define D 32
#define NN (NSEQ*NSEQ)        // 102400
#define LN_EPS 1e-5f

// ---- scratch (device globals; no allocation) ----
__device__ float g_x[NN*C];      // layernormed act
__device__ float g_q[NN*C];      // pre-scaled
__device__ float g_k[NN*C];
__device__ float g_v[NN*C];
__device__ float g_gate[NN*C];   // sigmoid applied
__device__ float g_bias[H*NN];   // TRANSPOSED: [h][k][q]
__device__ float g_wa[NN*C];     // attention out * gate
__device__ int   g_idx[NN];      // [b][j] compacted valid-k indices
__device__ int   g_cnt[NSEQ];    // valid count per b

typedef unsigned long long u64;

// ---------- tf32 mma helpers (base sm_103) ----------
__device__ __forceinline__ uint32_t tf32b(float x) {
    uint32_t u; asm("cvt.rna.tf32.f32 %0, %1;" : "=r"(u) : "f"(x)); return u;
}
__device__ __forceinline__ void split_tf32(float x, uint32_t& hi, uint32_t& lo) {
    hi = tf32b(x);
    lo = tf32b(x - __uint_as_float(hi));
}
__device__ __forceinline__ void mma8(float* d_, const uint32_t* a, const uint32_t* b) {
    asm volatile(
        "mma.sync.aligned.m16n8k8.row.col.f32.tf32.tf32.f32 "
        "{%0,%1,%2,%3}, {%4,%5,%6,%7}, {%8,%9}, {%0,%1,%2,%3};"
        : "+f"(d_[0]), "+f"(d_[1]), "+f"(d_[2]), "+f"(d_[3])
        : "r"(a[0]), "r"(a[1]), "r"(a[2]), "r"(a[3]), "r"(b[0]), "r"(b[1]));
}

// ============================================================
// Kernel 0: per-b deterministic compaction of valid k columns.
// ============================================================
__global__ void compact_kernel(const int* __restrict__ pm) {
    int b = blockIdx.x;
    int t = threadIdx.x;                     // 0..319
    __shared__ int wcnt[10], woff[10];
    int valid = (pm[(size_t)t * NSEQ + b] > 0) ? 1 : 0;
    unsigned ball = __ballot_sync(0xffffffffu, valid);
    int warp = t >> 5, lane = t & 31;
    if (lane == 0) wcnt[warp] = __popc(ball);
    __syncthreads();
    if (t == 0) {
        int s = 0;
        #pragma unroll
        for (int w = 0; w < 10; w++) { woff[w] = s; s += wcnt[w]; }
        g_cnt[b] = s;
    }
    __syncthreads();
    if (valid) {
        int pos = woff[warp] + __popc(ball & ((1u << lane) - 1u));
        g_idx[b * NSEQ + pos] = t;
    }
}

// ============================================================
// Kernel 1: LayerNorm + fused pair-bias projection (C->H).
// ============================================================
__global__ void ln_bias_kernel(const float* __restrict__ act,
                               const float* __restrict__ gamma,
                               const float* __restrict__ beta,
                               const float* __restrict__ wpb) {
    int warp = (blockIdx.x * blockDim.x + threadIdx.x) >> 5;
    int lane = threadIdx.x & 31;
    if (warp >= NN) return;
    const float4* a = (const float4*)(act + (size_t)warp * C);
    float4 v = a[lane];
    float s  = v.x + v.y + v.z + v.w;
    float s2 = v.x*v.x + v.y*v.y + v.z*v.z + v.w*v.w;
    #pragma unroll
    for (int o = 16; o > 0; o >>= 1) {
        s  += __shfl_xor_sync(0xffffffffu, s,  o);
        s2 += __shfl_xor_sync(0xffffffffu, s2, o);
    }
    float mu  = s * (1.0f / C);
    float var = s2 * (1.0f / C) - mu * mu;
    float r = rsqrtf(var + LN_EPS);
    float4 g = ((const float4*)gamma)[lane];
    float4 b = ((const float4*)beta)[lane];
    float4 o;
    o.x = (v.x - mu) * r * g.x + b.x;
    o.y = (v.y - mu) * r * g.y + b.y;
    o.z = (v.z - mu) * r * g.z + b.z;
    o.w = (v.w - mu) * r * g.w + b.w;
    ((float4*)(g_x + (size_t)warp * C))[lane] = o;

    const float4* wb = (const float4*)(wpb + lane * 16);
    float4 w0 = wb[0], w1 = wb[1], w2 = wb[2], w3 = wb[3];
    float bh[4];
    bh[0] = o.x*w0.x + o.y*w1.x + o.z*w2.x + o.w*w3.x;
    bh[1] = o.x*w0.y + o.y*w1.y + o.z*w2.y + o.w*w3.y;
    bh[2] = o.x*w0.z + o.y*w1.z + o.z*w2.z + o.w*w3.z;
    bh[3] = o.x*w0.w + o.y*w1.w + o.z*w2.w + o.w*w3.w;
    #pragma unroll
    for (int h = 0; h < 4; h++) {
        #pragma unroll
        for (int off = 16; off > 0; off >>= 1)
            bh[h] += __shfl_xor_sync(0xffffffffu, bh[h], off);
    }
    if (lane == 0) {
        int qi = warp / NSEQ;
        int kj = warp - qi * NSEQ;
        #pragma unroll
        for (int h = 0; h < 4; h++)
            g_bias[h*NN + kj*NSEQ + qi] = bh[h];   // store [h][k][q]
    }
}

// ============================================================
// Kernel 2: projection GEMMs via mma.sync tf32 (3xTF32 split).
// ============================================================
__global__ void __launch_bounds__(256)
proj_mma(const float* __restrict__ wq, const float* __restrict__ wk,
         const float* __restrict__ wv, const float* __restrict__ wg) {
    __shared__ __align__(16) float As[128*36];
    __shared__ __align__(16) float Bs[32*132];
    int op = blockIdx.x;
    const float* W = (op == 0) ? wq : (op == 1) ? wk : (op == 2) ? wv : wg;
    float* dst = (op == 0) ? g_q : (op == 1) ? g_k : (op == 2) ? g_v : g_gate;
    int bm = blockIdx.y * 128;
    int tid = threadIdx.x;
    int wid = tid >> 5, lane = tid & 31;
    int wm = (wid >> 2) * 64, wn = (wid & 3) * 32;
    int lr = lane >> 2, lc = lane & 3;

    float acc[4][4][4];
    #pragma unroll
    for (int mi = 0; mi < 4; mi++)
        #pragma unroll
        for (int ni = 0; ni < 4; ni++)
            #pragma unroll
            for (int e = 0; e < 4; e++) acc[mi][ni][e] = 0.0f;

    for (int k0 = 0; k0 < C; k0 += 32) {
        #pragma unroll
        for (int i = 0; i < 4; i++) {
            int e = i * 256 + tid;
            int r = e >> 3, c = (e & 7) * 4;
            float4 v = *(const float4*)(g_x + (size_t)(bm + r) * C + k0 + c);
            As[r*36 + c] = v.x; As[r*36 + c + 1] = v.y;
            As[r*36 + c + 2] = v.z; As[r*36 + c + 3] = v.w;
        }
        #pragma unroll
        for (int i = 0; i < 4; i++) {
            int e = i * 256 + tid;
            int r = e >> 5, c = (e & 31) * 4;
            *(float4*)&Bs[r*132 + c] = *(const float4*)(W + (size_t)(k0 + r) * C + c);
        }
        __syncthreads();
        #pragma unroll
        for (int kc = 0; kc < 4; kc++) {
            int kb = kc * 8 + lc;
            uint32_t ahi[4][4], alo[4][4];
            #pragma unroll
            for (int mi = 0; mi < 4; mi++) {
                int r0 = wm + mi * 16 + lr;
                split_tf32(As[r0*36 + kb],       ahi[mi][0], alo[mi][0]);
                split_tf32(As[(r0+8)*36 + kb],   ahi[mi][1], alo[mi][1]);
                split_tf32(As[r0*36 + kb + 4],   ahi[mi][2], alo[mi][2]);
                split_tf32(As[(r0+8)*36 + kb+4], ahi[mi][3], alo[mi][3]);
            }
            uint32_t bhi[4][2], blo[4][2];
            #pragma unroll
            for (int ni = 0; ni < 4; ni++) {
                int n0 = wn + ni * 8 + lr;
                split_tf32(Bs[kb*132 + n0],       bhi[ni][0], blo[ni][0]);
                split_tf32(Bs[(kb+4)*132 + n0],   bhi[ni][1], blo[ni][1]);
            }
            #pragma unroll
            for (int mi = 0; mi < 4; mi++)
                #pragma unroll
                for (int ni = 0; ni < 4; ni++) {
                    mma8(acc[mi][ni], ahi[mi], bhi[ni]);
                    mma8(acc[mi][ni], ahi[mi], blo[ni]);
                    mma8(acc[mi][ni], alo[mi], bhi[ni]);
                }
        }
        __syncthreads();
    }

    const float qscale = 0.17677669529663687f;   // 1/sqrt(32)
    #pragma unroll
    for (int mi = 0; mi < 4; mi++) {
        #pragma unroll
        for (int ni = 0; ni < 4; ni++) {
            int row = bm + wm + mi * 16 + lr;
            int col = wn + ni * 8 + 2 * lc;
            float v0 = acc[mi][ni][0], v1 = acc[mi][ni][1];
            float v2 = acc[mi][ni][2], v3 = acc[mi][ni][3];
            if (op == 0) { v0 *= qscale; v1 *= qscale; v2 *= qscale; v3 *= qscale; }
            else if (op == 3) {
                v0 = 1.0f/(1.0f+__expf(-v0)); v1 = 1.0f/(1.0f+__expf(-v1));
                v2 = 1.0f/(1.0f+__expf(-v2)); v3 = 1.0f/(1.0f+__expf(-v3));
            }
            *(float2*)(dst + (size_t)row * C + col)     = make_float2(v0, v1);
            *(float2*)(dst + (size_t)(row+8) * C + col) = make_float2(v2, v3);
        }
    }
}

// ============================================================
// Kernel 3: tensor-core flash attention over compacted keys.
// grid (b, h, 2 q-halves); 160 threads = 5 warps x 32 q-rows.
// S = Q K^T (+bias preloaded in accumulator), exp, P via smem, P V.
// ============================================================
#define KC 16

__global__ void __launch_bounds__(160, 2)
attn_mma() {
    __shared__ __align__(16) float Ks[KC][36];       // [key][d]
    __shared__ float Vt[D][17];                       // [d][key]
    __shared__ __align__(16) float Bsm[KC][164];      // [key][q-local]
    __shared__ float Ps[5][32][18];                   // per-warp P tile

    int b = blockIdx.x, h = blockIdx.y;
    int qbase = blockIdx.z * 160;
    int tid = threadIdx.x, wid = tid >> 5, lane = tid & 31;
    int lr = lane >> 2, lc = lane & 3;
    int cnt = g_cnt[b];
    const int* idxp = g_idx + b * NSEQ;

    // ---- preload Q fragments (hi/lo), 32 q-rows per warp ----
    uint32_t qhi[2][4][4], qlo[2][4][4];
    {
        const float* qp = g_q + (size_t)(b * NSEQ) * C + h * D;
        #pragma unroll
        for (int mi = 0; mi < 2; mi++) {
            int r0 = qbase + wid * 32 + mi * 16 + lr;
            #pragma unroll
            for (int kcc = 0; kcc < 4; kcc++) {
                int c0 = kcc * 8 + lc;
                split_tf32(qp[(size_t)r0 * C + c0],         qhi[mi][kcc][0], qlo[mi][kcc][0]);
                split_tf32(qp[(size_t)(r0 + 8) * C + c0],   qhi[mi][kcc][1], qlo[mi][kcc][1]);
                split_tf32(qp[(size_t)r0 * C + c0 + 4],     qhi[mi][kcc][2], qlo[mi][kcc][2]);
                split_tf32(qp[(size_t)(r0 + 8) * C + c0+4], qhi[mi][kcc][3], qlo[mi][kcc][3]);
            }
        }
    }

    float acc[2][4][4];
    #pragma unroll
    for (int mi = 0; mi < 2; mi++)
        #pragma unroll
        for (int ni = 0; ni < 4; ni++)
            #pragma unroll
            for (int e = 0; e < 4; e++) acc[mi][ni][e] = 0.0f;
    float lsum[2][2] = {{0.0f, 0.0f}, {0.0f, 0.0f}};

    int nch = (cnt + KC - 1) >> 4;
    for (int ch = 0; ch < nch; ch++) {
        int jc = ch << 4;
        __syncthreads();
        // ---- stage K + V^T (threads 0..127) ----
        if (tid < 128) {
            int key = tid >> 3, dd = (tid & 7) * 4;
            int j = jc + key;
            int kg = idxp[(j < cnt) ? j : 0];
            size_t base = ((size_t)(b * NSEQ) + kg) * C + h * D + dd;
            float4 kv = *(const float4*)(g_k + base);
            *(float4*)&Ks[key][dd] = kv;
            float4 vv = *(const float4*)(g_v + base);
            Vt[dd+0][key] = vv.x; Vt[dd+1][key] = vv.y;
            Vt[dd+2][key] = vv.z; Vt[dd+3][key] = vv.w;
        }
        // ---- stage bias tile [16][160] (pad keys -> -1e4 => p=0 exactly) ----
        #pragma unroll
        for (int i = 0; i < 4; i++) {
            int e = i * 160 + tid;              // 0..639
            int key = e / 40, c4 = (e - key * 40) * 4;
            int j = jc + key;
            float4 bv;
            if (j < cnt) {
                int kg = idxp[j];
                bv = *(const float4*)(g_bias + (size_t)h * NN + (size_t)kg * NSEQ + qbase + c4);
            } else bv = make_float4(-1e4f, -1e4f, -1e4f, -1e4f);
            *(float4*)&Bsm[key][c4] = bv;
        }
        __syncthreads();

        // ---- S = Q K^T with bias-preloaded accumulator ----
        float sc[2][2][4];
        int ql = wid * 32;
        #pragma unroll
        for (int mi = 0; mi < 2; mi++) {
            int q0 = ql + mi * 16 + lr;
            #pragma unroll
            for (int ni = 0; ni < 2; ni++) {
                int kl = ni * 8 + 2 * lc;
                sc[mi][ni][0] = Bsm[kl][q0];
                sc[mi][ni][1] = Bsm[kl + 1][q0];
                sc[mi][ni][2] = Bsm[kl][q0 + 8];
                sc[mi][ni][3] = Bsm[kl + 1][q0 + 8];
            }
        }
        #pragma unroll
        for (int kcc = 0; kcc < 4; kcc++) {
            uint32_t bhi[2][2], blo[2][2];
            #pragma unroll
            for (int ni = 0; ni < 2; ni++) {
                int n0 = ni * 8 + lr, kb = kcc * 8 + lc;
                split_tf32(Ks[n0][kb],     bhi[ni][0], blo[ni][0]);
                split_tf32(Ks[n0][kb + 4], bhi[ni][1], blo[ni][1]);
            }
            #pragma unroll
            for (int mi = 0; mi < 2; mi++)
                #pragma unroll
                for (int ni = 0; ni < 2; ni++) {
                    mma8(sc[mi][ni], qhi[mi][kcc], bhi[ni]);
                    mma8(sc[mi][ni], qhi[mi][kcc], blo[ni]);
                    mma8(sc[mi][ni], qlo[mi][kcc], bhi[ni]);
                }
        }
        // ---- exp, l accumulation, stash P ----
        #pragma unroll
        for (int mi = 0; mi < 2; mi++)
            #pragma unroll
            for (int ni = 0; ni < 2; ni++) {
                float p0 = __expf(sc[mi][ni][0]);
                float p1 = __expf(sc[mi][ni][1]);
                float p2 = __expf(sc[mi][ni][2]);
                float p3 = __expf(sc[mi][ni][3]);
                lsum[mi][0] += p0 + p1;
                lsum[mi][1] += p2 + p3;
                int r0 = mi * 16 + lr, cc = ni * 8 + 2 * lc;
                *(float2*)&Ps[wid][r0][cc]     = make_float2(p0, p1);
                *(float2*)&Ps[wid][r0 + 8][cc] = make_float2(p2, p3);
            }
        __syncwarp();
        // ---- O += P V ----
        #pragma unroll
        for (int kcc = 0; kcc < 2; kcc++) {
            uint32_t phi[2][4], plo[2][4];
            #pragma unroll
            for (int mi = 0; mi < 2; mi++) {
                int r0 = mi * 16 + lr, kb = kcc * 8 + lc;
                split_tf32(Ps[wid][r0][kb],         phi[mi][0], plo[mi][0]);
                split_tf32(Ps[wid][r0 + 8][kb],     phi[mi][1], plo[mi][1]);
                split_tf32(Ps[wid][r0][kb + 4],     phi[mi][2], plo[mi][2]);
                split_tf32(Ps[wid][r0 + 8][kb + 4], phi[mi][3], plo[mi][3]);
            }
            #pragma unroll
            for (int ni = 0; ni < 4; ni++) {
                uint32_t vhi[2], vlo[2];
                int n0 = ni * 8 + lr, kb = kcc * 8 + lc;
                split_tf32(Vt[n0][kb],     vhi[0], vlo[0]);
                split_tf32(Vt[n0][kb + 4], vhi[1], vlo[1]);
                #pragma unroll
                for (int mi = 0; mi < 2; mi++) {
                    mma8(acc[mi][ni], phi[mi], vhi);
                    mma8(acc[mi][ni], phi[mi], vlo);
                    mma8(acc[mi][ni], plo[mi], vhi);
                }
            }
        }
        __syncwarp();
    }

    // ---- normalize + gate + write ----
    float inv[2][2];
    #pragma unroll
    for (int mi = 0; mi < 2; mi++)
        #pragma unroll
        for (int e = 0; e < 2; e++) {
            float lf = lsum[mi][e];
            lf += __shfl_xor_sync(0xffffffffu, lf, 1);
            lf += __shfl_xor_sync(0xffffffffu, lf, 2);
            inv[mi][e] = (lf > 0.0f) ? 1.0f / lf : 0.0f;
        }
    #pragma unroll
    for (int mi = 0; mi < 2; mi++) {
        int qg = b * NSEQ + qbase + wid * 32 + mi * 16 + lr;
        #pragma unroll
        for (int ni = 0; ni < 4; ni++) {
            int dcol = h * D + ni * 8 + 2 * lc;
            size_t o0 = (size_t)qg * C + dcol;
            float2 gt0 = *(const float2*)(g_gate + o0);
            *(float2*)(g_wa + o0) =
                make_float2(acc[mi][ni][0] * inv[mi][0] * gt0.x,
                            acc[mi][ni][1] * inv[mi][0] * gt0.y);
            size_t o1 = o0 + (size_t)8 * C;
            float2 gt1 = *(const float2*)(g_gate + o1);
            *(float2*)(g_wa + o1) =
                make_float2(acc[mi][ni][2] * inv[mi][1] * gt1.x,
                            acc[mi][ni][3] * inv[mi][1] * gt1.y);
        }
    }
}

// ============================================================
// Kernel 4: output GEMM (wa)[NN,128] @ w_out^T via mma.sync tf32.
// ============================================================
__global__ void __launch_bounds__(256)
out_mma(const float* __restrict__ wout, float* __restrict__ out) {
    __shared__ __align__(16) float As[128*36];
    __shared__ __align__(16) float Bs[128*36];
    int bm = blockIdx.x * 128;
    int tid = threadIdx.x;
    int wid = tid >> 5, lane = tid & 31;
    int wm = (wid >> 2) * 64, wn = (wid & 3) * 32;
    int lr = lane >> 2, lc = lane & 3;

    float acc[4][4][4];
    #pragma unroll
    for (int mi = 0; mi < 4; mi++)
        #pragma unroll
        for (int ni = 0; ni < 4; ni++)
            #pragma unroll
            for (int e = 0; e < 4; e++) acc[mi][ni][e] = 0.0f;

    for (int k0 = 0; k0 < C; k0 += 32) {
        #pragma unroll
        for (int i = 0; i < 4; i++) {
            int e = i * 256 + tid;
            int r = e >> 3, c = (e & 7) * 4;
            float4 v = *(const float4*)(g_wa + (size_t)(bm + r) * C + k0 + c);
            As[r*36 + c] = v.x; As[r*36 + c + 1] = v.y;
            As[r*36 + c + 2] = v.z; As[r*36 + c + 3] = v.w;
            float4 w4 = *(const float4*)(wout + (size_t)r * C + k0 + c);
            *(float4*)&Bs[r*36 + c] = w4;
        }
        __syncthreads();
        #pragma unroll
        for (int kc = 0; kc < 4; kc++) {
            int kb = kc * 8 + lc;
            uint32_t ahi[4][4], alo[4][4];
            #pragma unroll
            for (int mi = 0; mi < 4; mi++) {
                int r0 = wm + mi * 16 + lr;
                split_tf32(As[r0*36 + kb],       ahi[mi][0], alo[mi][0]);
                split_tf32(As[(r0+8)*36 + kb],   ahi[mi][1], alo[mi][1]);
                split_tf32(As[r0*36 + kb + 4],   ahi[mi][2], alo[mi][2]);
                split_tf32(As[(r0+8)*36 + kb+4], ahi[mi][3], alo[mi][3]);
            }
            uint32_t bhi[4][2], blo[4][2];
            #pragma unroll
            for (int ni = 0; ni < 4; ni++) {
                int n0 = wn + ni * 8 + lr;
                split_tf32(Bs[n0*36 + kb],     bhi[ni][0], blo[ni][0]);
                split_tf32(Bs[n0*36 + kb + 4], bhi[ni][1], blo[ni][1]);
            }
            #pragma unroll
            for (int mi = 0; mi < 4; mi++)
                #pragma unroll
                for (int ni = 0; ni < 4; ni++) {
                    mma8(acc[mi][ni], ahi[mi], bhi[ni]);
                    mma8(acc[mi][ni], ahi[mi], blo[ni]);
                    mma8(acc[mi][ni], alo[mi], bhi[ni]);
                }
        }
        __syncthreads();
    }

    #pragma unroll
    for (int mi = 0; mi < 4; mi++) {
        #pragma unroll
        for (int ni = 0; ni < 4; ni++) {
            int row = bm + wm + mi * 16 + lr;
            int col = wn + ni * 8 + 2 * lc;
            *(float2*)(out + (size_t)row * C + col)
                = make_float2(acc[mi][ni][0], acc[mi][ni][1]);
            *(float2*)(out + (size_t)(row+8) * C + col)
                = make_float2(acc[mi][ni][2], acc[mi][ni][3]);
        }
    }
}

// ============================================================
extern "C" void kernel_launch(void* const* d_in, const int* in_sizes, int n_in,
                              void* d_out, int out_size) {
    const float* act   = (const float*)d_in[0];
    const int*   pmask = (const int*)  d_in[1];
    const float* gamma = (const float*)d_in[2];
    const float* beta  = (const float*)d_in[3];
    const float* wpb   = (const float*)d_in[4];
    const float* wq    = (const float*)d_in[5];
    const float* wk    = (const float*)d_in[6];
    const float* wv    = (const float*)d_in[7];
    const float* wg    = (const float*)d_in[8];
    const float* wout  = (const float*)d_in[9];
    float* out = (float*)d_out;

    compact_kernel<<<NSEQ, NSEQ>>>(pmask);
    ln_bias_kernel<<<NN/8, 256>>>(act, gamma, beta, wpb);
    proj_mma<<<dim3(4, NN/128), 256>>>(wq, wk, wv, wg);
    attn_mma<<<dim3(NSEQ, H, 2), 160>>>();
    out_mma<<<NN/128, 256>>>(wout, out);
}